// round 17
// baseline (speedup 1.0000x reference)
#include <cuda_runtime.h>
#include <math.h>

// ---------------- device scratch ----------------
__device__ float g_blur[4 * 224 * 224 * 256];   // blurred feats, layout [b][y][x][c]
__device__ float g_wp[81 * 256];                // weights repacked [k*9+tap][c]
__device__ int   g_mask_mode;                   // 0=uint8, 1=int32, 2=float32

// ---------------- mask dtype detection ----------------
__global__ void detect_mask_kernel(const unsigned* __restrict__ m) {
    int lane = threadIdx.x;  // 32 threads
    int fcount = 0, zocount = 0;
#pragma unroll
    for (int i = 0; i < 8; i++) {
        unsigned w = m[lane * 8 + i];
        if (w == 0x3f800000u) fcount++;
        if (w <= 1u) zocount++;
    }
#pragma unroll
    for (int o = 16; o; o >>= 1) {
        fcount  += __shfl_xor_sync(0xffffffffu, fcount, o);
        zocount += __shfl_xor_sync(0xffffffffu, zocount, o);
    }
    if (lane == 0) g_mask_mode = (fcount > 0) ? 2 : ((zocount == 256) ? 1 : 0);
}

// ---------------- weight repack: (9,256,3,3) -> [k*9+tap][c] ----------------
__global__ void repack_kernel(const float* __restrict__ ak) {
    int idx = blockIdx.x * 256 + threadIdx.x;  // 81 blocks * 256 = 20736
    int c  = idx & 255;
    int kt = idx >> 8;           // k*9 + tap, 0..80
    int k = kt / 9, tap = kt - k * 9;
    g_wp[idx] = ak[(k * 256 + c) * 9 + tap];
}

// ---------------- separable 5x5 gaussian blur (proven R3 config) -----------
#define BLUR_SMEM (32 * 593 * 4)

__global__ void __launch_bounds__(512, 2) blur_kernel(const float* __restrict__ hr) {
    extern __shared__ float s_v[];

    const float C = -1.4142135623730951f;
    float tb[5]; float s = 0.f;
#pragma unroll
    for (int j = 0; j < 5; j++) { float d = (float)(j - 2); tb[j] = expf(d * d * C); s += tb[j]; }
#pragma unroll
    for (int j = 0; j < 5; j++) tb[j] = tb[j] / s;

    int b = blockIdx.z, cb = blockIdx.y;
    int tx = blockIdx.x % 7, ty = blockIdx.x / 7;
    int x0 = tx * 32, y0 = ty * 16;
    int t = threadIdx.x;

    for (int j = t; j < 1152; j += 512) {
        int ch = j / 36, lx = j - ch * 36;
        int ix = x0 - 2 + lx;
        bool vx = (ix >= 0 && ix < 224);
        const float* base = hr + ((long)(b * 256 + cb * 32 + ch) * 224) * 224 + ix;
        float w0 = 0.f, w1 = 0.f, w2 = 0.f, w3 = 0.f, w4 = 0.f;
        float* ov = s_v + ch * 593 + lx;
#pragma unroll
        for (int yy = 0; yy < 20; yy++) {
            int iy = y0 - 2 + yy;
            float v = (vx && iy >= 0 && iy < 224) ? base[iy * 224] : 0.f;
            w0 = w1; w1 = w2; w2 = w3; w3 = w4; w4 = v;
            if (yy >= 4) {
                float o = w0*tb[0] + w1*tb[1] + w2*tb[2] + w3*tb[3] + w4*tb[4];
                ov[(yy - 4) * 37] = o;
            }
        }
    }
    __syncthreads();

    {
        int ch = t & 31, yr = t >> 5;
        const float* vp = s_v + ch * 593 + yr * 37;
        float* ob = g_blur + ((long)(b * 224 + y0 + yr) * 224 + x0) * 256 + cb * 32 + ch;
        float a0 = vp[0], a1 = vp[1], a2 = vp[2], a3 = vp[3];
#pragma unroll
        for (int x = 0; x < 32; x++) {
            float a4 = vp[x + 4];
            float o = a0*tb[0] + a1*tb[1] + a2*tb[2] + a3*tb[3] + a4*tb[4];
            ob[x * 256] = o;
            a0 = a1; a1 = a2; a2 = a3; a3 = a4;
        }
    }
}

// ---------------- fused v13: persistent weights in SMEM, 2x4 tiles ---------
// Grid = 148 CTAs, 512 threads, 1 CTA/SM, 6272 tiles (2x4 output each).
// Weights (83 KB) staged into SMEM ONCE; region double-buffered via cp.async.
// Phase B is barrier-free: thread = (kg = t>>8 [k 0-4 / 5-8], r = (t>>7)&1,
//   c2 = t&127). acc[KN][4]; per dy: ve[5]+vo[4] loaded once, 3 dx reuse.
// Region rows (5 riy x 9 rix, parity split):
//   even rix: row = riy*5 + rix/2 (25) ; odd rix: row = 25 + riy*4 + rix/2 (20)
// smem floats: s_blur 2x11700 | s_w 20736 | s_red 2304 | s_logit 72 | s_attn 72
#define GRID_F 148
#define TILES_TOTAL 6272
#define FUSED_SMEM ((23400 + 20736 + 2304 + 72 + 72) * 4)

// issue cp.async for tile's 45-row region into s_dst (zero-fill OOB)
__device__ __forceinline__ void prefetch_region(int tile, float* s_dst, int t) {
    int b = tile / 1568;
    int rem = tile - b * 1568;
    int ty = rem / 28, tx = rem - ty * 28;
    int rx0 = 2 * (tx * 4) - 1, ry0 = 2 * (ty * 2) - 1;
    int c4 = t & 63, rr = t >> 6;   // rr 0..7
    const float* gb = g_blur + (long)b * 224 * 224 * 256 + c4 * 4;
#pragma unroll
    for (int row = rr; row < 45; row += 8) {
        int riy, rix;
        if (row < 25) { riy = row / 5;  rix = 2 * (row - riy * 5); }
        else { int q = row - 25; riy = q >> 2; rix = 2 * (q & 3) + 1; }
        int iy = ry0 + riy, ix = rx0 + rix;
        bool ok = (iy >= 0 && iy < 224 && ix >= 0 && ix < 224);
        const float* src = ok ? (gb + ((long)iy * 224 + ix) * 256) : gb;
        unsigned dst = (unsigned)__cvta_generic_to_shared(s_dst + row * 260 + c4 * 4);
        int sz = ok ? 16 : 0;
        asm volatile("cp.async.cg.shared.global [%0], [%1], 16, %2;\n"
                     :: "r"(dst), "l"(src), "r"(sz));
    }
}

template<int K0, int KN>
__device__ __forceinline__ void phaseB_body(
    const float2* __restrict__ sb2, const float2* __restrict__ sw2,
    float* __restrict__ s_red, int c2, int r, int cblk, int lane)
{
    float acc[KN][4];
#pragma unroll
    for (int k = 0; k < KN; k++)
#pragma unroll
        for (int x = 0; x < 4; x++) acc[k][x] = 0.f;

#pragma unroll
    for (int dy = 0; dy < 3; dy++) {
        int riy = 2 * r + dy;
        int eb = riy * 5;         // even-rix rows base
        int ob = 25 + riy * 4;    // odd-rix rows base
        float2 ve[5], vo[4];
#pragma unroll
        for (int j = 0; j < 5; j++) ve[j] = sb2[(eb + j) * 130 + c2];
#pragma unroll
        for (int j = 0; j < 4; j++) vo[j] = sb2[(ob + j) * 130 + c2];

#pragma unroll
        for (int dx = 0; dx < 3; dx++) {
            int tap = dy * 3 + dx;
#pragma unroll
            for (int k = 0; k < KN; k++) {
                float2 w = sw2[((K0 + k) * 9 + tap) * 128 + c2];
#pragma unroll
                for (int x = 0; x < 4; x++) {
                    float2 v = (dx == 1) ? vo[x] : ve[x + (dx >> 1)];
                    acc[k][x] = fmaf(v.y, w.y, fmaf(v.x, w.x, acc[k][x]));
                }
            }
        }
    }

    // 2-level butterfly: lanes 0..7 hold sums of 4 lanes
#pragma unroll
    for (int o = 16; o >= 8; o >>= 1)
#pragma unroll
        for (int k = 0; k < KN; k++)
#pragma unroll
            for (int x = 0; x < 4; x++)
                acc[k][x] += __shfl_xor_sync(0xffffffffu, acc[k][x], o);

    if (lane < 8) {
#pragma unroll
        for (int k = 0; k < KN; k++)
            *(float4*)(s_red + (((K0 + k) * 2 + r) * 32 + cblk * 8 + lane) * 4) =
                make_float4(acc[k][0], acc[k][1], acc[k][2], acc[k][3]);
    }
}

__global__ void __launch_bounds__(512) fused_kernel(
    const void* __restrict__ maskp,
    const float* __restrict__ kbias,
    const float* __restrict__ lbias,
    float* __restrict__ out)
{
    extern __shared__ float sm[];
    float* s_blurA = sm;             // 2 x 11700
    float* s_w     = sm + 23400;     // 20736 (persistent weights)
    float* s_red   = sm + 44136;     // 2304 = 9k x 2r x 32 partials x 4 x
    float* s_logit = sm + 46440;     // 72
    float* s_attn  = sm + 46512;     // 72

    int t = threadIdx.x;
    int mm = g_mask_mode;

    float kb_r = 0.f, lb_r = 0.f;
    if (t < 72) { int k = t % 9; kb_r = kbias[k]; lb_r = lbias[k]; }

    // ---- stage ALL weights once (persistent across tiles) ----
    {
        const float4* wp4 = (const float4*)g_wp;
        float4* sw4 = (float4*)s_w;
        for (int i = t; i < 5184; i += 512) sw4[i] = __ldg(&wp4[i]);
    }

    int n = blockIdx.x;
    int buf = 0;

    prefetch_region(n, s_blurA, t);
    asm volatile("cp.async.commit_group;\n");

    while (n < TILES_TOTAL) {
        int n2 = n + GRID_F;
        if (n2 < TILES_TOTAL)
            prefetch_region(n2, s_blurA + (buf ^ 1) * 11700, t);
        asm volatile("cp.async.commit_group;\n");   // (possibly empty)

        asm volatile("cp.async.wait_group 1;\n");   // tile n's region resident
        __syncthreads();                            // also covers weight init (1st iter)

        float* s_blur = s_blurA + buf * 11700;
        int b = n / 1568;
        int rem = n - b * 1568;
        int tyi = rem / 28, txi = rem - tyi * 28;
        int x0o = txi * 4, y0o = tyi * 2;

        // ---- phase B: barrier-free logits ----
        {
            int c2 = t & 127;
            int r  = (t >> 7) & 1;
            int kg = t >> 8;
            int w = t >> 5, lane = t & 31;
            int cblk = w & 3;
            const float2* sb2 = (const float2*)s_blur;
            const float2* sw2 = (const float2*)s_w;
            if (kg == 0) phaseB_body<0, 5>(sb2, sw2, s_red, c2, r, cblk, lane);
            else         phaseB_body<5, 4>(sb2, sw2, s_red, c2, r, cblk, lane);
        }
        __syncthreads();

        // ---- combine 32 partials + kbias + mask + lbias -> masked logits ----
        if (t < 72) {
            int p = t / 9, k = t - p * 9;
            int r = p >> 2, x = p & 3;
            const float* rp = s_red + ((k * 2 + r) * 32) * 4 + x;
            float s0 = 0.f, s1 = 0.f, s2 = 0.f, s3 = 0.f;
#pragma unroll
            for (int j = 0; j < 32; j += 4) {
                s0 += rp[(j + 0) * 4];
                s1 += rp[(j + 1) * 4];
                s2 += rp[(j + 2) * 4];
                s3 += rp[(j + 3) * 4];
            }
            float v = kb_r + ((s0 + s1) + (s2 + s3));
            int oy = y0o + r, ox = x0o + x;
            long midx = ((long)(b * 9 + k) * 112 + oy) * 112 + ox;
            bool keep;
            if (mm == 0)      keep = ((const unsigned char*)maskp)[midx] != 0;
            else if (mm == 1) keep = ((const int*)maskp)[midx] != 0;
            else              keep = ((const float*)maskp)[midx] != 0.f;
            s_logit[p * 9 + k] = (keep ? v : 0.f) + lb_r;
        }
        __syncthreads();

        // ---- softmax over 9 ----
        if (t < 8) {
            int p = t;
            float lg[9];
#pragma unroll
            for (int k = 0; k < 9; k++) lg[k] = s_logit[p * 9 + k];
            float mx = lg[0];
#pragma unroll
            for (int k = 1; k < 9; k++) mx = fmaxf(mx, lg[k]);
            float e[9]; float ssum = 0.f;
#pragma unroll
            for (int k = 0; k < 9; k++) { e[k] = expf(lg[k] - mx); ssum += e[k]; }
            float invs = 1.0f / ssum;
#pragma unroll
            for (int k = 0; k < 9; k++) s_attn[p * 9 + k] = e[k] * invs;
        }
        __syncthreads();

        // ---- einsum: thread = (x = t&3, c4 = (t>>2)&63, r = t>>8) ----
        {
            int x = t & 3, c4 = (t >> 2) & 63, r = t >> 8;
            const float4* sb4 = (const float4*)s_blur;   // row stride 65
            float4 o = make_float4(0.f, 0.f, 0.f, 0.f);
#pragma unroll
            for (int dy = 0; dy < 3; dy++) {
                int riy = 2 * r + dy;
#pragma unroll
                for (int dx = 0; dx < 3; dx++) {
                    int rix = 2 * x + dx;
                    int row = (rix & 1) ? (25 + riy * 4 + (rix >> 1))
                                        : (riy * 5 + (rix >> 1));
                    float4 v = sb4[row * 65 + c4];
                    float a = s_attn[(r * 4 + x) * 9 + dy * 3 + dx];
                    o.x = fmaf(v.x, a, o.x);
                    o.y = fmaf(v.y, a, o.y);
                    o.z = fmaf(v.z, a, o.z);
                    o.w = fmaf(v.w, a, o.w);
                }
            }
            long base = ((long)(b * 256 + c4 * 4) * 112 + y0o + r) * 112 + x0o + x;
            const long cs = (long)112 * 112;
            out[base]          = o.x;
            out[base + cs]     = o.y;
            out[base + 2 * cs] = o.z;
            out[base + 3 * cs] = o.w;
        }
        __syncthreads();   // protect region buffer & s_attn before next tile

        buf ^= 1;
        n = n2;
    }
}

// ---------------- launch ----------------
extern "C" void kernel_launch(void* const* d_in, const int* in_sizes, int n_in,
                              void* d_out, int out_size) {
    const float* hr  = (const float*)d_in[0];
    const float* ak  = (const float*)d_in[1];
    const float* kb  = (const float*)d_in[2];
    const float* lb  = (const float*)d_in[3];
    const void*  msk = d_in[4];
    float* out = (float*)d_out;
    (void)in_sizes; (void)n_in; (void)out_size;

    cudaFuncSetAttribute(blur_kernel,  cudaFuncAttributeMaxDynamicSharedMemorySize, BLUR_SMEM);
    cudaFuncSetAttribute(fused_kernel, cudaFuncAttributeMaxDynamicSharedMemorySize, FUSED_SMEM);

    detect_mask_kernel<<<1, 32>>>((const unsigned*)msk);
    repack_kernel<<<81, 256>>>(ak);
    blur_kernel<<<dim3(98, 8, 4), 512, BLUR_SMEM>>>(hr);
    fused_kernel<<<GRID_F, 512, FUSED_SMEM>>>(msk, kb, lb, out);
}